// round 3
// baseline (speedup 1.0000x reference)
#include <cuda_runtime.h>
#include <math.h>

// Problem constants
#define BB   8
#define NN   64
#define EMBD 32
#define CDIM 24
#define HH   100
#define CONV 216     // 24*1 + 24*3 + 24*5
#define CO   248     // CLOUD_OUT
#define RO   496
#define FFW  128

// -------- device scratch (no allocations allowed) --------
__device__ float g_Wfe[6 * 101 * 80];        // per-embedding contracted radial weights (padded lu->80)
__device__ float g_o[BB * NN * CONV];        // atomically accumulated conv output
__device__ float g_feats[BB * NN * CO];      // [512,248]
__device__ float g_x2[BB * NN * CO];         // residual pre-BN
__device__ float g_pooled[BB * RO];          // [8,496]
__device__ float g_outacc[BB];               // final logits accumulator

__device__ __forceinline__ float sp5(float x) {
    // softplus(5x)/5, numerically stable
    float z = 5.0f * x;
    return 0.2f * (fmaxf(z, 0.0f) + log1pf(__expf(-fabsf(z))));
}

// ---------------- zero scratch ----------------
__global__ void kZero() {
    int idx = blockIdx.x * blockDim.x + threadIdx.x;
    if (idx < BB * NN * CONV) g_o[idx] = 0.0f;
    if (idx < BB) g_outacc[idx] = 0.0f;
}

// ---------------- Wfe[e][k][lu] = sum_v rW3[k, lu*32+v] * emb[e,v] / sqrt(32); row 100 = rb3 ----------------
__global__ void kWfe(const float* __restrict__ rW3, const float* __restrict__ rb3,
                     const float* __restrict__ emb) {
    __shared__ float sRowT[32 * 73];   // transposed row, stride 73 to kill bank conflicts
    __shared__ float sEmb[32];
    int e  = blockIdx.x / 101;
    int kk = blockIdx.x % 101;
    int tid = threadIdx.x;  // 128 threads
    const float* src = (kk < 100) ? (rW3 + kk * 2304) : rb3;
    for (int idx = tid; idx < 2304; idx += 128) {
        int lu = idx >> 5, v = idx & 31;
        sRowT[v * 73 + lu] = src[idx];
    }
    if (tid < 32) sEmb[tid] = emb[e * 32 + tid];
    __syncthreads();
    if (tid < 80) {
        float out = 0.0f;
        if (tid < 72) {
            float acc = 0.0f;
            #pragma unroll
            for (int v = 0; v < 32; v++) acc += sRowT[v * 73 + tid] * sEmb[v];
            out = acc * 0.17677669529663687f;   // 1/sqrt(32)
        }
        g_Wfe[e * 8080 + kk * 80 + tid] = out;
    }
}

// ---------------- main per-(b, neighbor j) kernel ----------------
// phase1: basis(3) -> h1(100); phase2: h1 -> h2 (100x100); phase3: t = h2 @ Wfe (+bias);
// phase4: scatter mask * Y_lm * t into g_o via atomics.
__global__ void __launch_bounds__(256) kPairs(
    const float* __restrict__ xyz, const int* __restrict__ feat,
    const float* __restrict__ rW1, const float* __restrict__ rb1,
    const float* __restrict__ rW2, const float* __restrict__ rb2) {

    extern __shared__ float sm[];
    float* sWf = sm;              // 101*80 = 8080
    float* sh1 = sm + 8080;       // [k][i] 100*64
    float* sh2 = sm + 14480;      // [k][i] 100*64
    float* sW2 = sm + 20880;      // [k1][k2 padded 112] 100*112
    float* sBa = sm + 32080;      // [3][64]
    float* sUx = sm + 32272;
    float* sUy = sm + 32336;
    float* sUz = sm + 32400;
    float* sMk = sm + 32464;      // total 32528 floats = 130112 B

    const int tid = threadIdx.x;
    const int b = blockIdx.x >> 6, j = blockIdx.x & 63;

    // load contracted radial weights for this neighbor's embedding
    {
        int e = feat[b * 64 + j];
        const float4* srcW = (const float4*)(g_Wfe + e * 8080);
        float4* dstW = (float4*)sWf;
        for (int idx = tid; idx < 2020; idx += 256) dstW[idx] = srcW[idx];
    }
    // load rW2 into padded shared
    for (int idx = tid; idx < 100 * 112; idx += 256) {
        int k1 = idx / 112, k2 = idx - k1 * 112;
        sW2[idx] = (k2 < 100) ? rW2[k1 * 100 + k2] : 0.0f;
    }
    // geometry for all centers i
    if (tid < 64) {
        int i = tid;
        float xj = xyz[(b * 64 + j) * 3 + 0];
        float yj = xyz[(b * 64 + j) * 3 + 1];
        float zj = xyz[(b * 64 + j) * 3 + 2];
        float dx = xj - xyz[(b * 64 + i) * 3 + 0];
        float dy = yj - xyz[(b * 64 + i) * 3 + 1];
        float dz = zj - xyz[(b * 64 + i) * 3 + 2];
        float d = sqrtf(dx * dx + dy * dy + dz * dz + 1e-8f);
        float inv = 1.0f / d;
        sUx[i] = dx * inv; sUy[i] = dy * inv; sUz[i] = dz * inv;
        sMk[i] = (d < 2.0f && i != j) ? 1.0f : 0.0f;
        #pragma unroll
        for (int r = 0; r < 3; r++) {
            float uu = fabsf(d - (float)r);
            float c = __cosf(1.57079632679f * uu);
            sBa[r * 64 + i] = (uu < 1.0f) ? c * c : 0.0f;
        }
    }
    __syncthreads();

    // phase 1: h1[k][i]
    for (int idx = tid; idx < 6400; idx += 256) {
        int k = idx >> 6, i = idx & 63;
        float z = rb1[k] + sBa[i] * rW1[k] + sBa[64 + i] * rW1[100 + k] + sBa[128 + i] * rW1[200 + k];
        sh1[idx] = sp5(z);
    }
    __syncthreads();

    // phase 2: h2 = sp(h1 @ rW2 + b2), thread tile 4i x 7k2
    {
        const int ig = tid >> 4, kg = tid & 15;
        const int i0 = ig << 2, k20 = kg * 7;
        float a0[7], a1[7], a2[7], a3[7];
        #pragma unroll
        for (int t = 0; t < 7; t++) { a0[t] = 0.f; a1[t] = 0.f; a2[t] = 0.f; a3[t] = 0.f; }
        const float* w2p = sW2 + k20;
        #pragma unroll 2
        for (int k1 = 0; k1 < 100; k1++) {
            float4 a = *(const float4*)(sh1 + (k1 << 6) + i0);
            const float* wr = w2p + k1 * 112;
            #pragma unroll
            for (int t = 0; t < 7; t++) {
                float w = wr[t];
                a0[t] += a.x * w; a1[t] += a.y * w; a2[t] += a.z * w; a3[t] += a.w * w;
            }
        }
        #pragma unroll
        for (int t = 0; t < 7; t++) {
            int k2 = k20 + t;
            if (k2 < 100) {
                float bb = rb2[k2];
                sh2[(k2 << 6) + i0 + 0] = sp5(a0[t] + bb);
                sh2[(k2 << 6) + i0 + 1] = sp5(a1[t] + bb);
                sh2[(k2 << 6) + i0 + 2] = sp5(a2[t] + bb);
                sh2[(k2 << 6) + i0 + 3] = sp5(a3[t] + bb);
            }
        }
    }
    __syncthreads();

    // phase 3: t[i][lu] = h2 @ Wfe + bias, thread tile 4i x 5lu ; phase 4: scatter with Y
    {
        const int ig = tid >> 4, lg = tid & 15;
        const int i0 = ig << 2, lu0 = lg * 5;
        float a0[5], a1[5], a2[5], a3[5];
        #pragma unroll
        for (int t = 0; t < 5; t++) {
            float bb = sWf[8000 + lu0 + t];
            a0[t] = bb; a1[t] = bb; a2[t] = bb; a3[t] = bb;
        }
        #pragma unroll 2
        for (int k = 0; k < 100; k++) {
            float4 a = *(const float4*)(sh2 + (k << 6) + i0);
            const float* wr = sWf + k * 80 + lu0;
            #pragma unroll
            for (int t = 0; t < 5; t++) {
                float w = wr[t];
                a0[t] += a.x * w; a1[t] += a.y * w; a2[t] += a.z * w; a3[t] += a.w * w;
            }
        }

        #define EMIT(ACC, MI)                                                              \
        {                                                                                  \
            int i = i0 + MI;                                                               \
            if (sMk[i] != 0.0f) {                                                          \
                float ux = sUx[i], uy = sUy[i], uz = sUz[i];                               \
                float* op = g_o + ((b << 6) + i) * 216;                                    \
                for (int t = 0; t < 5; t++) {                                              \
                    int lu = lu0 + t;                                                      \
                    if (lu < 72) {                                                         \
                        float v = ACC[t];                                                  \
                        if (lu < 24) {                                                     \
                            atomicAdd(op + lu, 0.28209479177f * v);                        \
                        } else if (lu < 48) {                                              \
                            int u = lu - 24; float s = 0.48860251190f * v;                 \
                            atomicAdd(op + 24 + u * 3 + 0, s * uy);                        \
                            atomicAdd(op + 24 + u * 3 + 1, s * uz);                        \
                            atomicAdd(op + 24 + u * 3 + 2, s * ux);                        \
                        } else {                                                           \
                            int u = lu - 48; float s = 1.09254843059f * v;                 \
                            atomicAdd(op + 96 + u * 5 + 0, s * ux * uy);                   \
                            atomicAdd(op + 96 + u * 5 + 1, s * uy * uz);                   \
                            atomicAdd(op + 96 + u * 5 + 2, 0.31539156525f * v * (3.0f * uz * uz - 1.0f)); \
                            atomicAdd(op + 96 + u * 5 + 3, s * ux * uz);                   \
                            atomicAdd(op + 96 + u * 5 + 4, 0.54627421529f * v * (ux * ux - uy * uy));     \
                        }                                                                  \
                    }                                                                      \
                }                                                                          \
            }                                                                              \
        }
        EMIT(a0, 0) EMIT(a1, 1) EMIT(a2, 2) EMIT(a3, 3)
        #undef EMIT
    }
}

// ---------------- feats assembly: [emb gather | conv * inv_deg] ----------------
__global__ void kFeats(const float* __restrict__ xyz, const int* __restrict__ feat,
                       const float* __restrict__ emb) {
    __shared__ float sM[64];
    __shared__ float sInv;
    int bi = blockIdx.x;
    int b = bi >> 6, i = bi & 63;
    int tid = threadIdx.x;  // 128
    if (tid < 64) {
        int jj = tid;
        float dx = xyz[(b * 64 + jj) * 3 + 0] - xyz[bi * 3 + 0];
        float dy = xyz[(b * 64 + jj) * 3 + 1] - xyz[bi * 3 + 1];
        float dz = xyz[(b * 64 + jj) * 3 + 2] - xyz[bi * 3 + 2];
        float d = sqrtf(dx * dx + dy * dy + dz * dz + 1e-8f);
        sM[jj] = (d < 2.0f && jj != i) ? 1.0f : 0.0f;
    }
    __syncthreads();
    if (tid == 0) {
        float s = 0.0f;
        for (int q = 0; q < 64; q++) s += sM[q];
        sInv = rsqrtf(fmaxf(s, 1.0f));
    }
    __syncthreads();
    int e = feat[bi];
    for (int c = tid; c < CO; c += 128) {
        float v = (c < 32) ? emb[e * 32 + c] : g_o[bi * 216 + (c - 32)] * sInv;
        g_feats[bi * CO + c] = v;
    }
}

// ---------------- residual linear: x2 = feats @ resW + resb ----------------
__global__ void kRes(const float* __restrict__ resW, const float* __restrict__ resb) {
    __shared__ float sF[8 * CO];
    int m0 = blockIdx.x * 8;   // 64 blocks
    int tid = threadIdx.x;     // 256
    for (int idx = tid; idx < 8 * CO; idx += 256) sF[idx] = g_feats[m0 * CO + idx];
    __syncthreads();
    if (tid < CO) {
        float acc[8];
        #pragma unroll
        for (int m = 0; m < 8; m++) acc[m] = 0.0f;
        for (int k4 = 0; k4 < CO / 4; k4++) {
            float w0 = resW[(k4 * 4 + 0) * CO + tid];
            float w1 = resW[(k4 * 4 + 1) * CO + tid];
            float w2 = resW[(k4 * 4 + 2) * CO + tid];
            float w3 = resW[(k4 * 4 + 3) * CO + tid];
            #pragma unroll
            for (int m = 0; m < 8; m++) {
                float4 a = *(const float4*)(sF + m * CO + k4 * 4);
                acc[m] += a.x * w0 + a.y * w1 + a.z * w2 + a.w * w3;
            }
        }
        float bb = resb[tid];
        #pragma unroll
        for (int m = 0; m < 8; m++) g_x2[(m0 + m) * CO + tid] = acc[m] + bb;
    }
}

// ---------------- per-column: BN(batch stats)+relu (for residual half) and mean-pool over N ----------------
__global__ void kPool(const float* __restrict__ gamma, const float* __restrict__ beta) {
    __shared__ float sP[8];
    __shared__ float rs[8], rss[8];
    __shared__ float sScale, sShift;
    int c = blockIdx.x;        // 0..495
    int tid = threadIdx.x;     // 256
    int lane = tid & 31, w = tid >> 5;
    if (tid < 8) sP[tid] = 0.0f;

    float v0, v1;
    if (c < CO) {
        v0 = g_feats[tid * CO + c];
        v1 = g_feats[(tid + 256) * CO + c];
    } else {
        int c2 = c - CO;
        v0 = g_x2[tid * CO + c2];
        v1 = g_x2[(tid + 256) * CO + c2];
        float s = v0 + v1, ss = v0 * v0 + v1 * v1;
        #pragma unroll
        for (int o = 16; o > 0; o >>= 1) {
            s  += __shfl_down_sync(0xffffffffu, s, o);
            ss += __shfl_down_sync(0xffffffffu, ss, o);
        }
        if (lane == 0) { rs[w] = s; rss[w] = ss; }
        __syncthreads();
        if (tid == 0) {
            float S = 0.0f, SS = 0.0f;
            for (int q = 0; q < 8; q++) { S += rs[q]; SS += rss[q]; }
            float mu = S * (1.0f / 512.0f);
            float var = SS * (1.0f / 512.0f) - mu * mu;
            float sc = gamma[c2] * rsqrtf(var + 1e-5f);
            sScale = sc;
            sShift = beta[c2] - mu * sc;
        }
        __syncthreads();
        v0 = fmaxf(v0 * sScale + sShift, 0.0f);
        v1 = fmaxf(v1 * sScale + sShift, 0.0f);
    }
    __syncthreads();
    // per-b mean pooling: warp w covers rows [32w,32w+32) -> b = w/2 ; rows+256 -> b+4
    float p0 = v0, p1 = v1;
    #pragma unroll
    for (int o = 16; o > 0; o >>= 1) {
        p0 += __shfl_down_sync(0xffffffffu, p0, o);
        p1 += __shfl_down_sync(0xffffffffu, p1, o);
    }
    if (lane == 0) {
        atomicAdd(&sP[w >> 1], p0);
        atomicAdd(&sP[4 + (w >> 1)], p1);
    }
    __syncthreads();
    if (tid < 8) g_pooled[tid * RO + c] = sP[tid] * (1.0f / 64.0f);
}

// ---------------- head: h2 = leaky(pooled @ cW + cb); BN over batch; leaky; accumulate @ oW ----------------
__global__ void kHead(const float* __restrict__ cW, const float* __restrict__ cb,
                      const float* __restrict__ cg, const float* __restrict__ cbeta,
                      const float* __restrict__ oW) {
    __shared__ float sPart[8][8];
    __shared__ float sV[8];
    __shared__ float sMu, sIs;
    int ff = blockIdx.x;       // 128
    int tid = threadIdx.x;     // 256
    int lane = tid & 31, w = tid >> 5;
    float p[8];
    #pragma unroll
    for (int q = 0; q < 8; q++) p[q] = 0.0f;
    for (int c = tid; c < RO; c += 256) {
        float wv = cW[c * FFW + ff];
        #pragma unroll
        for (int q = 0; q < 8; q++) p[q] += g_pooled[q * RO + c] * wv;
    }
    #pragma unroll
    for (int q = 0; q < 8; q++) {
        #pragma unroll
        for (int o = 16; o > 0; o >>= 1) p[q] += __shfl_down_sync(0xffffffffu, p[q], o);
    }
    if (lane == 0) {
        #pragma unroll
        for (int q = 0; q < 8; q++) sPart[q][w] = p[q];
    }
    __syncthreads();
    if (tid < 8) {
        float h = cb[ff];
        for (int q = 0; q < 8; q++) h += sPart[tid][q];
        sV[tid] = (h > 0.0f) ? h : 0.01f * h;
    }
    __syncthreads();
    if (tid == 0) {
        float S = 0.0f, SS = 0.0f;
        for (int q = 0; q < 8; q++) { S += sV[q]; SS += sV[q] * sV[q]; }
        float mu = S * 0.125f;
        sMu = mu;
        sIs = rsqrtf(SS * 0.125f - mu * mu + 1e-5f);
    }
    __syncthreads();
    if (tid < 8) {
        float v = (sV[tid] - sMu) * sIs * cg[ff] + cbeta[ff];
        v = (v > 0.0f) ? v : 0.01f * v;
        atomicAdd(&g_outacc[tid], v * oW[ff]);
    }
}

// ---------------- final sigmoid ----------------
__global__ void kOut(float* __restrict__ out, const float* __restrict__ ob) {
    int tid = threadIdx.x;
    if (tid < 8) out[tid] = 1.0f / (1.0f + __expf(-(g_outacc[tid] + ob[0])));
}

extern "C" void kernel_launch(void* const* d_in, const int* in_sizes, int n_in,
                              void* d_out, int out_size) {
    const float* xyz   = (const float*)d_in[0];
    const int*   feat  = (const int*)  d_in[1];
    const float* emb   = (const float*)d_in[2];
    const float* rW1   = (const float*)d_in[3];
    const float* rb1   = (const float*)d_in[4];
    const float* rW2   = (const float*)d_in[5];
    const float* rb2   = (const float*)d_in[6];
    const float* rW3   = (const float*)d_in[7];
    const float* rb3   = (const float*)d_in[8];
    const float* resW  = (const float*)d_in[9];
    const float* resb  = (const float*)d_in[10];
    const float* resg  = (const float*)d_in[11];
    const float* resbe = (const float*)d_in[12];
    const float* cW    = (const float*)d_in[13];
    const float* cb    = (const float*)d_in[14];
    const float* cg    = (const float*)d_in[15];
    const float* cbe   = (const float*)d_in[16];
    const float* oW    = (const float*)d_in[17];
    const float* ob    = (const float*)d_in[18];
    float* out = (float*)d_out;

    cudaFuncSetAttribute(kPairs, cudaFuncAttributeMaxDynamicSharedMemorySize, 130112);

    kZero<<<432, 256>>>();
    kWfe<<<606, 128>>>(rW3, rb3, emb);
    kPairs<<<512, 256, 130112>>>(xyz, feat, rW1, rb1, rW2, rb2);
    kFeats<<<512, 128>>>(xyz, feat, emb);
    kRes<<<64, 256>>>(resW, resb);
    kPool<<<496, 256>>>(resg, resbe);
    kHead<<<128, 256>>>(cW, cb, cg, cbe, oW);
    kOut<<<1, 32>>>(out, ob);
}